// round 15
// baseline (speedup 1.0000x reference)
#include <cuda_runtime.h>
#include <cuda_bf16.h>
#include <math.h>
#include <stdint.h>

#define NB 8
#define C 256
#define C2 128
#define P 4096          // 64*64 pixels
#define COUT3 768
#define KFULL 1024      // 768 gated channels + 256 raw x channels

// ---------------- scratch (device globals; no allocs allowed) ----------------
__device__ float g_pos[C * P];                 // positional encoding, 4 MB
__device__ float g_expx[NB * COUT3 * P];       // X = expx + pos (stored fused)
__device__ float g_wcov[P];                    // coverage weights for win=6
__device__ float g_chw[3][NB * C];             // channel gate
__device__ float g_v[3][NB * C];               // spatial-gate projection vector
__device__ float g_beta[3][NB];                // spatial-gate bias
__device__ float g_bc[C];                      // W_fus @ b_res + b_fus
__device__ float g_zb[C];                      // zero bias (never written)
__device__ float g_Wcf[C * COUT3];             // fp32 Wc (gated part)
__device__ float g_posout[C * P];              // Wsum @ pos, 4 MB
// per-block partials for the fused tq+red reduction (P/128 = 32 blocks)
__device__ float g_pxs[3][NB][32][C];
__device__ float g_pys[3][NB][32][C];
__device__ float g_pz[3][NB][32];

// pre-split operands (bf16 hi/lo)
__device__ __nv_bfloat16 g_WexpH[COUT3 * C], g_WexpL[COUT3 * C];
__device__ __nv_bfloat16 g_WcatH[C * KFULL], g_WcatL[C * KFULL];
__device__ __nv_bfloat16 g_WsumH[C * C], g_WsumL[C * C];
__device__ __nv_bfloat16 g_xh[NB * P * C], g_xl[NB * P * C];   // [n][p][c]
__device__ __nv_bfloat16 g_pth[P * C], g_ptl[P * C];           // pos [p][c] split

// ================= helpers =================
__device__ __forceinline__ uint32_t smem_u32(const void* p) {
    uint32_t a;
    asm("{ .reg .u64 t; cvta.to.shared.u64 t, %1; cvt.u32.u64 %0, t; }"
        : "=r"(a) : "l"(p));
    return a;
}
__device__ __forceinline__ uint32_t swz(uint32_t b) { return b ^ ((b >> 3) & 0x70); }

__device__ __forceinline__ void split2(float a, float b, uint32_t& hp, uint32_t& lp) {
    __nv_bfloat16 ha = __float2bfloat16_rn(a);
    __nv_bfloat16 hb = __float2bfloat16_rn(b);
    __nv_bfloat16 la = __float2bfloat16_rn(a - __bfloat162float(ha));
    __nv_bfloat16 lb = __float2bfloat16_rn(b - __bfloat162float(hb));
    hp = (uint32_t)__bfloat16_as_ushort(ha) | ((uint32_t)__bfloat16_as_ushort(hb) << 16);
    lp = (uint32_t)__bfloat16_as_ushort(la) | ((uint32_t)__bfloat16_as_ushort(lb) << 16);
}

__device__ __forceinline__ void ldsm4(uint32_t a[4], uint32_t addr) {
    asm volatile("ldmatrix.sync.aligned.m8n8.x4.shared.b16 {%0,%1,%2,%3}, [%4];"
                 : "=r"(a[0]), "=r"(a[1]), "=r"(a[2]), "=r"(a[3]) : "r"(addr));
}
__device__ __forceinline__ void mma16816(float d[4], const uint32_t a[4],
                                         const uint32_t b0, const uint32_t b1) {
    asm("mma.sync.aligned.m16n8k16.row.col.f32.bf16.bf16.f32 "
        "{%0,%1,%2,%3}, {%4,%5,%6,%7}, {%8,%9}, {%0,%1,%2,%3};"
        : "+f"(d[0]), "+f"(d[1]), "+f"(d[2]), "+f"(d[3])
        : "r"(a[0]), "r"(a[1]), "r"(a[2]), "r"(a[3]), "r"(b0), "r"(b1));
}
__device__ __forceinline__ void cpasync16(uint32_t dst, const void* src) {
    asm volatile("cp.async.ca.shared.global [%0], [%1], 16;" :: "r"(dst), "l"(src));
}
__device__ __forceinline__ void cp_commit() {
    asm volatile("cp.async.commit_group;" ::: "memory");
}
__device__ __forceinline__ void cp_wait1() {
    asm volatile("cp.async.wait_group 1;" ::: "memory");
}

// 12 MMAs for one A hi/lo pair against both B nip-halves.
__device__ __forceinline__ void mma_block(float acc[4][4],
                                          const uint32_t aH[4], const uint32_t aL[4],
                                          const uint32_t bH[2][4], const uint32_t bL[2][4]) {
    mma16816(acc[0], aH, bH[0][0], bH[0][1]);
    mma16816(acc[1], aH, bH[0][2], bH[0][3]);
    mma16816(acc[2], aH, bH[1][0], bH[1][1]);
    mma16816(acc[3], aH, bH[1][2], bH[1][3]);
    mma16816(acc[0], aH, bL[0][0], bL[0][1]);
    mma16816(acc[1], aH, bL[0][2], bL[0][3]);
    mma16816(acc[2], aH, bL[1][0], bL[1][1]);
    mma16816(acc[3], aH, bL[1][2], bL[1][3]);
    mma16816(acc[0], aL, bH[0][0], bH[0][1]);
    mma16816(acc[1], aL, bH[0][2], bH[0][3]);
    mma16816(acc[2], aL, bH[1][0], bH[1][1]);
    mma16816(acc[3], aL, bH[1][2], bH[1][3]);
}

// ======= GEMM (generic): Y[n,o,p] = sum_c A[o,c] B[n,p,c] + bias (+pos) =======
// 3-slot ring, ONE __syncthreads per chunk. B parameterized (stride BK).
#define STG 32768
#define SM_BYTES (3 * STG)

__global__ void __launch_bounds__(256, 2)
gemm_mma4(const __nv_bfloat16* __restrict__ WH, const __nv_bfloat16* __restrict__ WL,
          const __nv_bfloat16* __restrict__ Bh, const __nv_bfloat16* __restrict__ Bl,
          int BK, const float* __restrict__ bias, float* __restrict__ Y,
          int Cin, int Cout, const float* __restrict__ pos_add)
{
    extern __shared__ char smem[];
    uint32_t sb = smem_u32(smem);
    int tid = threadIdx.x, wid = tid >> 5, lane = tid & 31;
    int n = blockIdx.z;
    int row0 = blockIdx.y * 128, col0 = blockIdx.x * 128;
    float* Yn = Y + (size_t)n * Cout * P;

    int warp_m = wid >> 2;
    int warp_n = wid & 3;

    float acc[4][4][4];
#pragma unroll
    for (int i = 0; i < 4; i++)
#pragma unroll
        for (int j = 0; j < 4; j++)
#pragma unroll
            for (int k = 0; k < 4; k++) acc[i][j][k] = 0.f;

    int l7 = lane & 7;
    int aRowOff = ((lane >> 3) & 1) * 8 + l7;
    int aKOff16 = (lane >> 4) * 16;
    int bRowOff = ((lane >> 4) & 1) * 8 + l7;
    int bColOff = ((lane >> 3) & 1) * 16;

    int nchunks = Cin >> 5;

    auto load_stage = [&](int ch, int s) {
        int c0 = ch << 5;
        uint32_t stA = sb + s * STG;
        uint32_t stB = stA + 16384;
#pragma unroll
        for (int i = 0; i < 4; i++) {
            int idx = i * 256 + tid;
            int row = idx >> 3, slot = idx & 7;
            int til = slot >> 2, q = slot & 3;
            const __nv_bfloat16* srcA =
                (til ? WL : WH) + (size_t)(row0 + row) * Cin + c0 + q * 8;
            cpasync16(stA + swz((uint32_t)(row * 128 + til * 64 + q * 16)), srcA);
            const __nv_bfloat16* srcB =
                (til ? Bl : Bh) + ((size_t)n * P + col0 + row) * BK + c0 + q * 8;
            cpasync16(stB + swz((uint32_t)(row * 128 + til * 64 + q * 16)), srcB);
        }
    };

    load_stage(0, 0);
    cp_commit();

    for (int ch = 0; ch < nchunks; ch++) {
        if (ch + 1 < nchunks) load_stage(ch + 1, (ch + 1) % 3);
        cp_commit();
        cp_wait1();
        __syncthreads();
        uint32_t stA = sb + (ch % 3) * STG;
        uint32_t stB = stA + 16384;
#pragma unroll
        for (int ks = 0; ks < 2; ks++) {
            int kb = ks * 32;
            uint32_t bH[2][4], bL[2][4];
#pragma unroll
            for (int nip = 0; nip < 2; nip++) {
                int row = warp_n * 32 + nip * 16 + bRowOff;
                ldsm4(bH[nip], stB + swz((uint32_t)(row * 128 + kb + bColOff)));
                ldsm4(bL[nip], stB + swz((uint32_t)(row * 128 + 64 + kb + bColOff)));
            }
#pragma unroll
            for (int mi = 0; mi < 4; mi++) {
                uint32_t aH[4], aL[4];
                int row = warp_m * 64 + mi * 16 + aRowOff;
                ldsm4(aH, stA + swz((uint32_t)(row * 128 + kb + aKOff16)));
                ldsm4(aL, stA + swz((uint32_t)(row * 128 + 64 + kb + aKOff16)));
                mma_block(acc[mi], aH, aL, bH, bL);
            }
        }
    }

    int r = lane >> 2, q = lane & 3;
#pragma unroll
    for (int mi = 0; mi < 4; mi++) {
        int o = row0 + warp_m * 64 + mi * 16 + r;
        float b0 = bias[o];
        float b8 = bias[o + 8];
#pragma unroll
        for (int ni = 0; ni < 4; ni++) {
            int p = col0 + warp_n * 32 + ni * 8 + q * 2;
            size_t i0 = (size_t)o * P + p;
            size_t i1 = (size_t)(o + 8) * P + p;
            float2 v0 = make_float2(acc[mi][ni][0] + b0, acc[mi][ni][1] + b0);
            float2 v1 = make_float2(acc[mi][ni][2] + b8, acc[mi][ni][3] + b8);
            if (pos_add) {
                size_t q0 = (size_t)(o & 255) * P + p;
                size_t q1 = (size_t)((o + 8) & 255) * P + p;
                float2 p0 = *(const float2*)&pos_add[q0];
                float2 p1 = *(const float2*)&pos_add[q1];
                v0.x += p0.x; v0.y += p0.y;
                v1.x += p1.x; v1.y += p1.y;
            }
            *(float2*)&Yn[i0] = v0;
            *(float2*)&Yn[i1] = v1;
        }
    }
}

// ======= GEMM2 (final): M=256 x N=64, pos factored into g_posout =======
#define FSTG 40960            // A 32 KB + B 8 KB
#define FSM_BYTES (2 * FSTG)

__global__ void __launch_bounds__(256, 2)
gemm_fin(const __nv_bfloat16* __restrict__ WH, const __nv_bfloat16* __restrict__ WL,
         const float* __restrict__ bias, float* __restrict__ Y)
{
    extern __shared__ char smem[];
    __shared__ float vsh[3 * C];
    __shared__ float cwsh[3 * C];
    __shared__ float redp[256];
    __shared__ float Ss[192];
    uint32_t sb = smem_u32(smem);
    int tid = threadIdx.x, wid = tid >> 5, lane = tid & 31;
    int n = blockIdx.z;
    int col0 = blockIdx.x * 64;
    float* Yn = Y + (size_t)n * C * P;

    // ---- prologue: load v + chw, compute S for this CTA's 64 pixels ----
    for (int i = tid; i < 3 * C; i += 256) {
        int b = i >> 8, c = i & 255;
        vsh[i] = g_v[b][n * C + c];
        cwsh[i] = g_chw[b][n * C + c];
    }
    __syncthreads();
    {
        int sx = tid & 63, sq = tid >> 6;
#pragma unroll 1
        for (int b = 0; b < 3; b++) {
            const float* Xb = g_expx + ((size_t)n * COUT3 + b * C + sq * 64) * P + col0 + sx;
            float a = 0.f;
#pragma unroll 8
            for (int c = 0; c < 64; c++) a += vsh[b * C + sq * 64 + c] * Xb[(size_t)c * P];
            redp[tid] = a;
            __syncthreads();
            if (tid < 64)
                Ss[b * 64 + tid] = 1.f / (1.f + expf(-(redp[tid] + redp[tid + 64] +
                                                      redp[tid + 128] + redp[tid + 192] +
                                                      g_beta[b][n])));
            __syncthreads();
        }
    }

    int warp_m = wid >> 1;
    int warp_n = wid & 1;

    float acc[4][4][4];
#pragma unroll
    for (int i = 0; i < 4; i++)
#pragma unroll
        for (int j = 0; j < 4; j++)
#pragma unroll
            for (int k = 0; k < 4; k++) acc[i][j][k] = 0.f;

    int l7 = lane & 7;
    int aRowOff = ((lane >> 3) & 1) * 8 + l7;
    int aKOff16 = (lane >> 4) * 16;
    int bRowOff = ((lane >> 4) & 1) * 8 + l7;
    int bColOff = ((lane >> 3) & 1) * 16;

    const int nchunks = KFULL >> 5;   // 32
    int ldrow = tid & 63, ldq = tid >> 6;
    int pg = col0 + ldrow;

    float vx[8];
    auto gather_gated = [&](int ch) {
        int c0 = ch << 5;
        const float* Xc = &g_expx[((size_t)n * COUT3 + c0 + ldq * 8) * P + pg];
#pragma unroll
        for (int i = 0; i < 8; i++) vx[i] = Xc[(size_t)i * P];
    };
    auto store_gated = [&](int ch, int s) {
        int c0 = ch << 5;
        char* smB = smem + s * FSTG + 32768;
        int b = c0 >> 8;
        float Sp1 = 1.f + Ss[b * 64 + ldrow];
        float val[8];
#pragma unroll
        for (int i = 0; i < 8; i++) {
            int cl = (c0 & 255) + ldq * 8 + i;
            val[i] = vx[i] * (Sp1 + cwsh[b * C + cl]);
        }
#pragma unroll
        for (int g = 0; g < 8; g += 4) {
            int kk = ldq * 8 + g;
            uint32_t h0, l0, h1, l1;
            split2(val[g], val[g + 1], h0, l0);
            split2(val[g + 2], val[g + 3], h1, l1);
            *(uint2*)(smB + swz((uint32_t)(ldrow * 128 + kk * 2))) = make_uint2(h0, h1);
            *(uint2*)(smB + swz((uint32_t)(ldrow * 128 + 64 + kk * 2))) = make_uint2(l0, l1);
        }
    };
    auto loadA = [&](int ch, int s) {
        int c0 = ch << 5;
        uint32_t stA = sb + s * FSTG;
#pragma unroll
        for (int i = 0; i < 8; i++) {
            int idx = i * 256 + tid;
            int row = idx >> 3, slot = idx & 7;
            int til = slot >> 2, q = slot & 3;
            const __nv_bfloat16* srcA =
                (til ? WL : WH) + (size_t)row * KFULL + c0 + q * 8;
            cpasync16(stA + swz((uint32_t)(row * 128 + til * 64 + q * 16)), srcA);
        }
    };
    auto loadB_x = [&](int ch, int s) {
        int c0 = ch << 5;
        uint32_t stB = sb + s * FSTG + 32768;
        int xc0 = c0 - COUT3;
#pragma unroll
        for (int i = 0; i < 2; i++) {
            int idx = i * 256 + tid;
            int row = idx >> 3, slot = idx & 7;
            int til = slot >> 2, q = slot & 3;
            const __nv_bfloat16* srcB =
                (til ? g_xl : g_xh) + ((size_t)n * P + col0 + row) * C + xc0 + q * 8;
            cpasync16(stB + swz((uint32_t)(row * 128 + til * 64 + q * 16)), srcB);
        }
    };

#pragma unroll
    for (int pre = 0; pre < 2; pre++) {
        loadA(pre, pre);
        if ((pre << 5) < COUT3) { gather_gated(pre); store_gated(pre, pre); }
        else loadB_x(pre, pre);
        cp_commit();
    }

    int s = 0;
    for (int ch = 0; ch < nchunks; ch++) {
        bool pre_gated = (ch + 2 < nchunks) && (((ch + 2) << 5) < COUT3);
        if (pre_gated) gather_gated(ch + 2);
        cp_wait1();
        __syncthreads();
        uint32_t stA = sb + s * FSTG;
        uint32_t stB = stA + 32768;
#pragma unroll
        for (int ks = 0; ks < 2; ks++) {
            int kb = ks * 32;
            uint32_t bH[2][4], bL[2][4];
#pragma unroll
            for (int nip = 0; nip < 2; nip++) {
                int row = warp_n * 32 + nip * 16 + bRowOff;
                ldsm4(bH[nip], stB + swz((uint32_t)(row * 128 + kb + bColOff)));
                ldsm4(bL[nip], stB + swz((uint32_t)(row * 128 + 64 + kb + bColOff)));
            }
#pragma unroll
            for (int mi = 0; mi < 4; mi++) {
                uint32_t aH[4], aL[4];
                int row = warp_m * 64 + mi * 16 + aRowOff;
                ldsm4(aH, stA + swz((uint32_t)(row * 128 + kb + aKOff16)));
                ldsm4(aL, stA + swz((uint32_t)(row * 128 + 64 + kb + aKOff16)));
                mma_block(acc[mi], aH, aL, bH, bL);
            }
        }
        __syncthreads();
        if (ch + 2 < nchunks) {
            loadA(ch + 2, s);
            if (pre_gated) store_gated(ch + 2, s);
            else loadB_x(ch + 2, s);
        }
        cp_commit();
        s ^= 1;
    }

    int r = lane >> 2, q = lane & 3;
#pragma unroll
    for (int mi = 0; mi < 4; mi++) {
        int o = warp_m * 64 + mi * 16 + r;
        float b0 = bias[o];
        float b8 = bias[o + 8];
#pragma unroll
        for (int ni = 0; ni < 4; ni++) {
            int p = col0 + warp_n * 32 + ni * 8 + q * 2;
            size_t i0 = (size_t)o * P + p;
            size_t i1 = (size_t)(o + 8) * P + p;
            float2 ps0 = *(const float2*)&g_posout[i0];
            float2 ps1 = *(const float2*)&g_posout[i1];
            *(float2*)&Yn[i0] = make_float2(acc[mi][ni][0] + b0 - ps0.x,
                                            acc[mi][ni][1] + b0 - ps0.y);
            *(float2*)&Yn[i1] = make_float2(acc[mi][ni][2] + b8 - ps1.x,
                                            acc[mi][ni][3] + b8 - ps1.y);
        }
    }
}

// ===== tqred: fused ch_wq logits + exp + per-channel partial reductions =====
__global__ __launch_bounds__(256) void tqred_kernel(const float* __restrict__ wq,
                                                    const float* __restrict__ bq) {
    int b = blockIdx.z, n = blockIdx.y, blk = blockIdx.x;
    int p0 = blk * 128;
    int tid = threadIdx.x;
    __shared__ float wqs[C], Wes[128], wcs[128], part[256];

    wqs[tid] = wq[tid];
    __syncthreads();

    {
        int px = tid & 127, half = tid >> 7;
        const float* Xb = g_expx + ((size_t)n * COUT3 + b * C + half * 128) * P + p0 + px;
        float a0 = 0.f, a1 = 0.f;
#pragma unroll 8
        for (int c = 0; c < 128; c += 2) {
            a0 += wqs[half * 128 + c] * Xb[(size_t)c * P];
            a1 += wqs[half * 128 + c + 1] * Xb[(size_t)(c + 1) * P];
        }
        part[tid] = a0 + a1;
    }
    __syncthreads();
    if (tid < 128) {
        float T = part[tid] + part[tid + 128] + bq[0];
        float w = (b == 2) ? g_wcov[p0 + tid] : 1.f;
        wcs[tid] = w;
        Wes[tid] = w * expf(T);
    }
    __syncthreads();

    if (tid < 32) {
        float z = Wes[tid] + Wes[tid + 32] + Wes[tid + 64] + Wes[tid + 96];
#pragma unroll
        for (int o = 16; o > 0; o >>= 1) z += __shfl_xor_sync(0xffffffffu, z, o);
        if (tid == 0) g_pz[b][n][blk] = z;
    }

    int w = tid >> 5, lane = tid & 31;
#pragma unroll 2
    for (int cc = 0; cc < 32; cc += 2) {
        int c = w * 32 + cc;
        const float* Xc0 = g_expx + ((size_t)n * COUT3 + b * C + c) * P + p0;
        const float* Xc1 = Xc0 + P;
        float xs0 = 0.f, ys0 = 0.f, xs1 = 0.f, ys1 = 0.f;
#pragma unroll
        for (int i = 0; i < 4; i++) {
            int p = lane + i * 32;
            float X0 = Xc0[p], X1 = Xc1[p];
            float wc = wcs[p], we = Wes[p];
            xs0 += wc * X0;
            ys0 += we * X0;
            xs1 += wc * X1;
            ys1 += we * X1;
        }
#pragma unroll
        for (int o = 16; o > 0; o >>= 1) {
            xs0 += __shfl_xor_sync(0xffffffffu, xs0, o);
            ys0 += __shfl_xor_sync(0xffffffffu, ys0, o);
            xs1 += __shfl_xor_sync(0xffffffffu, xs1, o);
            ys1 += __shfl_xor_sync(0xffffffffu, ys1, o);
        }
        if (lane == 0) {
            g_pxs[b][n][blk][c] = xs0;
            g_pys[b][n][blk][c] = ys0;
            g_pxs[b][n][blk][c + 1] = xs1;
            g_pys[b][n][blk][c + 1] = ys1;
        }
    }
}

// =========================== prep kernels ===========================
__global__ void wsplit_kernel(const float* __restrict__ W,
                              __nv_bfloat16* __restrict__ H,
                              __nv_bfloat16* __restrict__ L, int total) {
    int idx = blockIdx.x * 256 + threadIdx.x;
    if (idx < total) {
        float v = W[idx];
        __nv_bfloat16 h = __float2bfloat16_rn(v);
        H[idx] = h;
        L[idx] = __float2bfloat16_rn(v - __bfloat162float(h));
    }
}

__global__ __launch_bounds__(256) void xprep_kernel(const float* __restrict__ x) {
    __shared__ float tile[32][33];
    int n = blockIdx.z;
    int p0 = blockIdx.x * 32, c0 = blockIdx.y * 32;
    int tx = threadIdx.x & 31, ty = threadIdx.x >> 5;
    for (int i = ty; i < 32; i += 8)
        tile[i][tx] = x[((size_t)n * C + c0 + i) * P + p0 + tx];
    __syncthreads();
    for (int i = ty; i < 32; i += 8) {
        float v = tile[tx][i];
        __nv_bfloat16 h = __float2bfloat16_rn(v);
        size_t dst = ((size_t)n * P + p0 + i) * C + c0 + tx;
        g_xh[dst] = h;
        g_xl[dst] = __float2bfloat16_rn(v - __bfloat162float(h));
    }
}

// transpose + split pos: [c][p] -> g_pth/g_ptl [p][c]
__global__ __launch_bounds__(256) void posTprep_kernel() {
    __shared__ float tile[32][33];
    int p0 = blockIdx.x * 32, c0 = blockIdx.y * 32;
    int tx = threadIdx.x & 31, ty = threadIdx.x >> 5;
    for (int i = ty; i < 32; i += 8)
        tile[i][tx] = g_pos[(size_t)(c0 + i) * P + p0 + tx];
    __syncthreads();
    for (int i = ty; i < 32; i += 8) {
        float v = tile[tx][i];
        __nv_bfloat16 h = __float2bfloat16_rn(v);
        size_t dst = (size_t)(p0 + i) * C + c0 + tx;
        g_pth[dst] = h;
        g_ptl[dst] = __float2bfloat16_rn(v - __bfloat162float(h));
    }
}

// wcat: blocks 0..KFULL-1 build [Wc | Wf] split (+fp32 Wc); block KFULL -> bc.
__global__ __launch_bounds__(256) void wcat_kernel(const float* __restrict__ Wf,
                                                   const float* __restrict__ Wr,
                                                   const float* __restrict__ br,
                                                   const float* __restrict__ bf) {
    int c = blockIdx.x;
    int o = threadIdx.x;
    if (c == KFULL) {
        float a = 0.f;
#pragma unroll 8
        for (int m = 0; m < C; m++) a += Wf[o * C + m] * br[m];
        g_bc[o] = a + bf[o];
        return;
    }
    float a;
    if (c < COUT3) {
        __shared__ float col[C];
        col[o] = Wr[o * COUT3 + c];
        __syncthreads();
        const float* row = Wf + o * C;
        a = 0.f;
#pragma unroll 8
        for (int m = 0; m < C; m++) a += row[m] * col[m];
        g_Wcf[o * COUT3 + c] = a;
    } else {
        a = Wf[o * C + (c - COUT3)];
    }
    __nv_bfloat16 h = __float2bfloat16_rn(a);
    g_WcatH[o * KFULL + c] = h;
    g_WcatL[o * KFULL + c] = __float2bfloat16_rn(a - __bfloat162float(h));
}

// Wsum[o,c2] = sum_b Wc[o, b*256+c2], split to bf16 hi/lo
__global__ __launch_bounds__(256) void wsum_kernel() {
    int c2 = blockIdx.x, o = threadIdx.x;
    float s = g_Wcf[o * COUT3 + c2] + g_Wcf[o * COUT3 + 256 + c2] +
              g_Wcf[o * COUT3 + 512 + c2];
    __nv_bfloat16 h = __float2bfloat16_rn(s);
    g_WsumH[o * C + c2] = h;
    g_WsumL[o * C + c2] = __float2bfloat16_rn(s - __bfloat162float(h));
}

// =========================== non-GEMM kernels ===========================
__device__ __forceinline__ int cov6(int h) {
    int r = 0;
#pragma unroll
    for (int j = 0; j < 6; j++) r += (h >= 10 * j) && (h <= 10 * j + 13);
    return r;
}
__device__ __forceinline__ float sigmoidf_(float x) { return 1.0f / (1.0f + expf(-x)); }

__global__ void pos_kernel() {
    int idx = blockIdx.x * blockDim.x + threadIdx.x;  // < C*P
    int prow = idx >> 8;
    int c = idx & 255;
    int i = prow >> 6;
    int j = prow & 63;
    int k = c & 63;
    float omega = exp2f((float)k * -0.2076245786f);
    float coord = (c < 128) ? (float)i : (float)j;
    float a = coord * omega;
    float val = ((c >> 6) & 1) ? cosf(a) : sinf(a);
    g_pos[idx] = val;
    if (idx < P) {
        int h = idx >> 6, w = idx & 63;
        g_wcov[idx] = (float)(cov6(h) * cov6(w));
    }
}

// tiny: folds the 32 per-block partials itself
__global__ __launch_bounds__(256) void tiny_kernel(
    const float* __restrict__ Wv, const float* __restrict__ bv,
    const float* __restrict__ Wz, const float* __restrict__ bz,
    const float* __restrict__ lg, const float* __restrict__ lb,
    const float* __restrict__ Wqs, const float* __restrict__ bqs,
    const float* __restrict__ Wvs, const float* __restrict__ bvs)
{
    int n = blockIdx.x, b = blockIdx.y;
    __shared__ float y[C], xb[C], zz[C2], sq[C2], wzs[C], red[256];
    int t = threadIdx.x;
    float L = (b == 2) ? 7056.f : 4096.f;

    float xs = 0.f, ys = 0.f;
#pragma unroll
    for (int k = 0; k < 32; k++) {
        xs += g_pxs[b][n][k][t];
        ys += g_pys[b][n][k][t];
    }
    float Zn = 0.f;
#pragma unroll
    for (int k = 0; k < 32; k++) Zn += g_pz[b][n][k];

    y[t] = ys / Zn;
    xb[t] = xs / L;
    __syncthreads();

    if (t < C2) {
        float a = 0.f;
        for (int c = 0; c < C; c++) a += Wv[t * C + c] * y[c];
        zz[t] = a + bv[t];
    }
    __syncthreads();

    {
        float a = 0.f;
        for (int c2 = 0; c2 < C2; c2++) a += Wz[t * C2 + c2] * zz[c2];
        wzs[t] = a + bz[t];
    }
    __syncthreads();

    red[t] = wzs[t]; __syncthreads();
    for (int s = 128; s > 0; s >>= 1) { if (t < s) red[t] += red[t + s]; __syncthreads(); }
    float m = red[0] / 256.f; __syncthreads();
    float d = wzs[t] - m;
    red[t] = d * d; __syncthreads();
    for (int s = 128; s > 0; s >>= 1) { if (t < s) red[t] += red[t + s]; __syncthreads(); }
    float var = red[0] / 256.f; __syncthreads();
    g_chw[b][n * C + t] = sigmoidf_(d * rsqrtf(var + 1e-5f) * lg[t] + lb[t]);

    if (t < C2) {
        float a = 0.f;
        for (int c = 0; c < C; c++) a += Wqs[t * C + c] * xb[c];
        zz[t] = a + bqs[t];
    }
    __syncthreads();
    red[t] = (t < C2) ? zz[t] : -1e30f; __syncthreads();
    for (int s = 128; s > 0; s >>= 1) { if (t < s) red[t] = fmaxf(red[t], red[t + s]); __syncthreads(); }
    float mx = red[0]; __syncthreads();
    float e = (t < C2) ? expf(zz[t] - mx) : 0.f;
    if (t < C2) sq[t] = e;
    red[t] = e; __syncthreads();
    for (int s = 128; s > 0; s >>= 1) { if (t < s) red[t] += red[t + s]; __syncthreads(); }
    float se = red[0]; __syncthreads();
    if (t < C2) sq[t] /= se;
    __syncthreads();

    {
        float a = 0.f;
        for (int c2 = 0; c2 < C2; c2++) a += sq[c2] * Wvs[c2 * C + t];
        g_v[b][n * C + t] = a;
    }
    red[t] = (t < C2) ? sq[t] * bvs[t] : 0.f; __syncthreads();
    for (int s = 128; s > 0; s >>= 1) { if (t < s) red[t] += red[t + s]; __syncthreads(); }
    if (t == 0) g_beta[b][n] = red[0];
}

// ---------------- host ----------------
extern "C" void kernel_launch(void* const* d_in, const int* in_sizes, int n_in,
                              void* d_out, int out_size) {
    const float* x       = (const float*)d_in[0];
    const float* w_exp   = (const float*)d_in[1];
    const float* b_exp   = (const float*)d_in[2];
    const float* w_res   = (const float*)d_in[3];
    const float* b_res   = (const float*)d_in[4];
    const float* w_fus   = (const float*)d_in[5];
    const float* b_fus   = (const float*)d_in[6];
    const float* ch_wv_w = (const float*)d_in[7];
    const float* ch_wv_b = (const float*)d_in[8];
    const float* ch_wq_w = (const float*)d_in[9];
    const float* ch_wq_b = (const float*)d_in[10];
    const float* ch_wz_w = (const float*)d_in[11];
    const float* ch_wz_b = (const float*)d_in[12];
    const float* ln_g    = (const float*)d_in[13];
    const float* ln_b    = (const float*)d_in[14];
    const float* sp_wv_w = (const float*)d_in[15];
    const float* sp_wv_b = (const float*)d_in[16];
    const float* sp_wq_w = (const float*)d_in[17];
    const float* sp_wq_b = (const float*)d_in[18];

    float *p_expx, *p_bc, *p_pos, *p_zb, *p_posout;
    __nv_bfloat16 *p_WexpH, *p_WexpL, *p_WcatH, *p_WcatL;
    __nv_bfloat16 *p_WsumH, *p_WsumL, *p_xh, *p_xl, *p_pth, *p_ptl;
    cudaGetSymbolAddress((void**)&p_expx, g_expx);
    cudaGetSymbolAddress((void**)&p_bc, g_bc);
    cudaGetSymbolAddress((void**)&p_pos, g_pos);
    cudaGetSymbolAddress((void**)&p_zb, g_zb);
    cudaGetSymbolAddress((void**)&p_posout, g_posout);
    cudaGetSymbolAddress((void**)&p_WexpH, g_WexpH);
    cudaGetSymbolAddress((void**)&p_WexpL, g_WexpL);
    cudaGetSymbolAddress((void**)&p_WcatH, g_WcatH);
    cudaGetSymbolAddress((void**)&p_WcatL, g_WcatL);
    cudaGetSymbolAddress((void**)&p_WsumH, g_WsumH);
    cudaGetSymbolAddress((void**)&p_WsumL, g_WsumL);
    cudaGetSymbolAddress((void**)&p_xh, g_xh);
    cudaGetSymbolAddress((void**)&p_xl, g_xl);
    cudaGetSymbolAddress((void**)&p_pth, g_pth);
    cudaGetSymbolAddress((void**)&p_ptl, g_ptl);

    cudaFuncSetAttribute(gemm_mma4,
                         cudaFuncAttributeMaxDynamicSharedMemorySize, SM_BYTES);
    cudaFuncSetAttribute(gemm_fin,
                         cudaFuncAttributeMaxDynamicSharedMemorySize, FSM_BYTES);

    pos_kernel<<<(C * P) / 256, 256>>>();
    posTprep_kernel<<<dim3(P / 32, C / 32), 256>>>();
    wcat_kernel<<<KFULL + 1, 256>>>(w_fus, w_res, b_res, b_fus);
    wsum_kernel<<<C, 256>>>();
    wsplit_kernel<<<COUT3, 256>>>(w_exp, p_WexpH, p_WexpL, COUT3 * C);
    xprep_kernel<<<dim3(P / 32, C / 32, NB), 256>>>(x);

    // g_posout = Wsum @ pos  (256x256x4096, once)
    gemm_mma4<<<dim3(P / 128, 2, 1), 256, SM_BYTES>>>(
        p_WsumH, p_WsumL, p_pth, p_ptl, C, p_zb, p_posout, C, C, nullptr);

    // g_expx = X = W_exp @ x + b_exp + pos  (pos fused in epilogue)
    gemm_mma4<<<dim3(P / 128, COUT3 / 128, NB), 256, SM_BYTES>>>(
        p_WexpH, p_WexpL, p_xh, p_xl, C, b_exp, p_expx, C, COUT3, p_pos);

    tqred_kernel<<<dim3(P / 128, NB, 3), 256>>>(ch_wq_w, ch_wq_b);
    tiny_kernel<<<dim3(NB, 3), 256>>>(ch_wv_w, ch_wv_b, ch_wz_w, ch_wz_b,
                                      ln_g, ln_b, sp_wq_w, sp_wq_b,
                                      sp_wv_w, sp_wv_b);

    // out = [Wc | W_fus] @ [gated-cat ; x] + bc - posout
    gemm_fin<<<dim3(P / 64, 1, NB), 256, FSM_BYTES>>>(
        p_WcatH, p_WcatL, p_bc, (float*)d_out);
}

// round 16
// speedup vs baseline: 1.0578x; 1.0578x over previous
#include <cuda_runtime.h>
#include <cuda_bf16.h>
#include <math.h>
#include <stdint.h>

#define NB 8
#define C 256
#define C2 128
#define P 4096          // 64*64 pixels
#define COUT3 768
#define KFULL 1024      // 768 gated channels + 256 raw x channels

// ---------------- scratch (device globals; no allocs allowed) ----------------
__device__ float g_pos[C * P];                 // positional encoding, 4 MB
__device__ float g_expx[NB * COUT3 * P];       // X = expx + pos (stored fused)
__device__ float g_wcov[P];                    // coverage weights for win=6
__device__ float g_chw[3][NB * C];             // channel gate
__device__ float g_v[3][NB * C];               // spatial-gate projection vector
__device__ float g_beta[3][NB];                // spatial-gate bias
__device__ float g_bc[C];                      // W_fus @ b_res + b_fus
// per-block partials for the fused tq+red reduction (P/128 = 32 blocks)
__device__ float g_pxs[3][NB][32][C];
__device__ float g_pys[3][NB][32][C];
__device__ float g_pz[3][NB][32];

// pre-split operands (bf16 hi/lo)
__device__ __nv_bfloat16 g_WexpH[COUT3 * C], g_WexpL[COUT3 * C];
__device__ __nv_bfloat16 g_WcatH[C * KFULL], g_WcatL[C * KFULL];
__device__ __nv_bfloat16 g_xh[NB * P * C], g_xl[NB * P * C];   // [n][p][c]

// ================= helpers =================
__device__ __forceinline__ uint32_t smem_u32(const void* p) {
    uint32_t a;
    asm("{ .reg .u64 t; cvta.to.shared.u64 t, %1; cvt.u32.u64 %0, t; }"
        : "=r"(a) : "l"(p));
    return a;
}
__device__ __forceinline__ uint32_t swz(uint32_t b) { return b ^ ((b >> 3) & 0x70); }

__device__ __forceinline__ void split2(float a, float b, uint32_t& hp, uint32_t& lp) {
    __nv_bfloat16 ha = __float2bfloat16_rn(a);
    __nv_bfloat16 hb = __float2bfloat16_rn(b);
    __nv_bfloat16 la = __float2bfloat16_rn(a - __bfloat162float(ha));
    __nv_bfloat16 lb = __float2bfloat16_rn(b - __bfloat162float(hb));
    hp = (uint32_t)__bfloat16_as_ushort(ha) | ((uint32_t)__bfloat16_as_ushort(hb) << 16);
    lp = (uint32_t)__bfloat16_as_ushort(la) | ((uint32_t)__bfloat16_as_ushort(lb) << 16);
}

__device__ __forceinline__ void ldsm4(uint32_t a[4], uint32_t addr) {
    asm volatile("ldmatrix.sync.aligned.m8n8.x4.shared.b16 {%0,%1,%2,%3}, [%4];"
                 : "=r"(a[0]), "=r"(a[1]), "=r"(a[2]), "=r"(a[3]) : "r"(addr));
}
__device__ __forceinline__ void mma16816(float d[4], const uint32_t a[4],
                                         const uint32_t b0, const uint32_t b1) {
    asm("mma.sync.aligned.m16n8k16.row.col.f32.bf16.bf16.f32 "
        "{%0,%1,%2,%3}, {%4,%5,%6,%7}, {%8,%9}, {%0,%1,%2,%3};"
        : "+f"(d[0]), "+f"(d[1]), "+f"(d[2]), "+f"(d[3])
        : "r"(a[0]), "r"(a[1]), "r"(a[2]), "r"(a[3]), "r"(b0), "r"(b1));
}
__device__ __forceinline__ void cpasync16(uint32_t dst, const void* src) {
    asm volatile("cp.async.ca.shared.global [%0], [%1], 16;" :: "r"(dst), "l"(src));
}
__device__ __forceinline__ void cp_commit() {
    asm volatile("cp.async.commit_group;" ::: "memory");
}
__device__ __forceinline__ void cp_wait1() {
    asm volatile("cp.async.wait_group 1;" ::: "memory");
}

// 12 MMAs for one A hi/lo pair against both B nip-halves.
__device__ __forceinline__ void mma_block(float acc[4][4],
                                          const uint32_t aH[4], const uint32_t aL[4],
                                          const uint32_t bH[2][4], const uint32_t bL[2][4]) {
    mma16816(acc[0], aH, bH[0][0], bH[0][1]);
    mma16816(acc[1], aH, bH[0][2], bH[0][3]);
    mma16816(acc[2], aH, bH[1][0], bH[1][1]);
    mma16816(acc[3], aH, bH[1][2], bH[1][3]);
    mma16816(acc[0], aH, bL[0][0], bL[0][1]);
    mma16816(acc[1], aH, bL[0][2], bL[0][3]);
    mma16816(acc[2], aH, bL[1][0], bL[1][1]);
    mma16816(acc[3], aH, bL[1][2], bL[1][3]);
    mma16816(acc[0], aL, bH[0][0], bH[0][1]);
    mma16816(acc[1], aL, bH[0][2], bH[0][3]);
    mma16816(acc[2], aL, bH[1][0], bH[1][1]);
    mma16816(acc[3], aL, bH[1][2], bH[1][3]);
}

// ======= GEMM1 (expx): Y[n,o,p] = sum_c A[o,c] B[c,p] + bias (+pos) =======
// 3-slot ring, ONE __syncthreads per chunk.
#define STG 32768
#define SM_BYTES (3 * STG)

__global__ void __launch_bounds__(256, 2)
gemm_mma4(const __nv_bfloat16* __restrict__ WH, const __nv_bfloat16* __restrict__ WL,
          const float* __restrict__ bias, float* __restrict__ Y,
          int Cin, int Cout, const float* __restrict__ pos_add)
{
    extern __shared__ char smem[];
    uint32_t sb = smem_u32(smem);
    int tid = threadIdx.x, wid = tid >> 5, lane = tid & 31;
    int n = blockIdx.z;
    int row0 = blockIdx.y * 128, col0 = blockIdx.x * 128;
    float* Yn = Y + (size_t)n * Cout * P;

    int warp_m = wid >> 2;
    int warp_n = wid & 3;

    float acc[4][4][4];
#pragma unroll
    for (int i = 0; i < 4; i++)
#pragma unroll
        for (int j = 0; j < 4; j++)
#pragma unroll
            for (int k = 0; k < 4; k++) acc[i][j][k] = 0.f;

    int l7 = lane & 7;
    int aRowOff = ((lane >> 3) & 1) * 8 + l7;
    int aKOff16 = (lane >> 4) * 16;
    int bRowOff = ((lane >> 4) & 1) * 8 + l7;
    int bColOff = ((lane >> 3) & 1) * 16;

    int nchunks = Cin >> 5;

    auto load_stage = [&](int ch, int s) {
        int c0 = ch << 5;
        uint32_t stA = sb + s * STG;
        uint32_t stB = stA + 16384;
#pragma unroll
        for (int i = 0; i < 4; i++) {
            int idx = i * 256 + tid;
            int row = idx >> 3, slot = idx & 7;
            int til = slot >> 2, q = slot & 3;
            const __nv_bfloat16* srcA =
                (til ? WL : WH) + (size_t)(row0 + row) * Cin + c0 + q * 8;
            cpasync16(stA + swz((uint32_t)(row * 128 + til * 64 + q * 16)), srcA);
            const __nv_bfloat16* srcB =
                (til ? g_xl : g_xh) + ((size_t)n * P + col0 + row) * C + c0 + q * 8;
            cpasync16(stB + swz((uint32_t)(row * 128 + til * 64 + q * 16)), srcB);
        }
    };

    load_stage(0, 0);
    cp_commit();

    for (int ch = 0; ch < nchunks; ch++) {
        if (ch + 1 < nchunks) load_stage(ch + 1, (ch + 1) % 3);
        cp_commit();
        cp_wait1();
        __syncthreads();
        uint32_t stA = sb + (ch % 3) * STG;
        uint32_t stB = stA + 16384;
#pragma unroll
        for (int ks = 0; ks < 2; ks++) {
            int kb = ks * 32;
            uint32_t bH[2][4], bL[2][4];
#pragma unroll
            for (int nip = 0; nip < 2; nip++) {
                int row = warp_n * 32 + nip * 16 + bRowOff;
                ldsm4(bH[nip], stB + swz((uint32_t)(row * 128 + kb + bColOff)));
                ldsm4(bL[nip], stB + swz((uint32_t)(row * 128 + 64 + kb + bColOff)));
            }
#pragma unroll
            for (int mi = 0; mi < 4; mi++) {
                uint32_t aH[4], aL[4];
                int row = warp_m * 64 + mi * 16 + aRowOff;
                ldsm4(aH, stA + swz((uint32_t)(row * 128 + kb + aKOff16)));
                ldsm4(aL, stA + swz((uint32_t)(row * 128 + 64 + kb + aKOff16)));
                mma_block(acc[mi], aH, aL, bH, bL);
            }
        }
    }

    int r = lane >> 2, q = lane & 3;
#pragma unroll
    for (int mi = 0; mi < 4; mi++) {
        int o = row0 + warp_m * 64 + mi * 16 + r;
        float b0 = bias[o];
        float b8 = bias[o + 8];
#pragma unroll
        for (int ni = 0; ni < 4; ni++) {
            int p = col0 + warp_n * 32 + ni * 8 + q * 2;
            size_t i0 = (size_t)o * P + p;
            size_t i1 = (size_t)(o + 8) * P + p;
            float2 v0 = make_float2(acc[mi][ni][0] + b0, acc[mi][ni][1] + b0);
            float2 v1 = make_float2(acc[mi][ni][2] + b8, acc[mi][ni][3] + b8);
            if (pos_add) {
                size_t q0 = (size_t)(o & 255) * P + p;
                size_t q1 = (size_t)((o + 8) & 255) * P + p;
                float2 p0 = *(const float2*)&pos_add[q0];
                float2 p1 = *(const float2*)&pos_add[q1];
                v0.x += p0.x; v0.y += p0.y;
                v1.x += p1.x; v1.y += p1.y;
            }
            *(float2*)&Yn[i0] = v0;
            *(float2*)&Yn[i1] = v1;
        }
    }
}

// ======= GEMM2 (final): M=256 x N=64, grid.y=1, S in prologue =======
// Gated B loads are register-prefetched one chunk ahead to hide LDG latency.
#define FSTG 40960            // A 32 KB + B 8 KB
#define FSM_BYTES (2 * FSTG)

__global__ void __launch_bounds__(256, 2)
gemm_fin(const __nv_bfloat16* __restrict__ WH, const __nv_bfloat16* __restrict__ WL,
         const float* __restrict__ bias, float* __restrict__ Y)
{
    extern __shared__ char smem[];
    __shared__ float vsh[3 * C];
    __shared__ float cwsh[3 * C];
    __shared__ float redp[256];
    __shared__ float Ss[192];
    uint32_t sb = smem_u32(smem);
    int tid = threadIdx.x, wid = tid >> 5, lane = tid & 31;
    int n = blockIdx.z;
    int col0 = blockIdx.x * 64;
    float* Yn = Y + (size_t)n * C * P;

    // ---- prologue: load v + chw, compute S for this CTA's 64 pixels ----
    for (int i = tid; i < 3 * C; i += 256) {
        int b = i >> 8, c = i & 255;
        vsh[i] = g_v[b][n * C + c];
        cwsh[i] = g_chw[b][n * C + c];
    }
    __syncthreads();
    {
        int sx = tid & 63, sq = tid >> 6;
#pragma unroll 1
        for (int b = 0; b < 3; b++) {
            const float* Xb = g_expx + ((size_t)n * COUT3 + b * C + sq * 64) * P + col0 + sx;
            float a = 0.f;
#pragma unroll 8
            for (int c = 0; c < 64; c++) a += vsh[b * C + sq * 64 + c] * Xb[(size_t)c * P];
            redp[tid] = a;
            __syncthreads();
            if (tid < 64)
                Ss[b * 64 + tid] = 1.f / (1.f + expf(-(redp[tid] + redp[tid + 64] +
                                                      redp[tid + 128] + redp[tid + 192] +
                                                      g_beta[b][n])));
            __syncthreads();
        }
    }

    int warp_m = wid >> 1;   // 0..3 -> 64 rows each (M=256)
    int warp_n = wid & 1;    // 0..1 -> 32 cols (N=64)

    float acc[4][4][4];
#pragma unroll
    for (int i = 0; i < 4; i++)
#pragma unroll
        for (int j = 0; j < 4; j++)
#pragma unroll
            for (int k = 0; k < 4; k++) acc[i][j][k] = 0.f;

    int l7 = lane & 7;
    int aRowOff = ((lane >> 3) & 1) * 8 + l7;
    int aKOff16 = (lane >> 4) * 16;
    int bRowOff = ((lane >> 4) & 1) * 8 + l7;
    int bColOff = ((lane >> 3) & 1) * 16;

    const int nchunks = KFULL >> 5;   // 32
    int ldrow = tid & 63, ldq = tid >> 6;  // gated-loader role
    int pg = col0 + ldrow;

    float vx[8], vp[8];
    auto gather_gated = [&](int ch) {
        int c0 = ch << 5;
        const float* Xc = &g_expx[((size_t)n * COUT3 + c0 + ldq * 8) * P + pg];
        const float* pc = &g_pos[(size_t)((c0 & 255) + ldq * 8) * P + pg];
#pragma unroll
        for (int i = 0; i < 8; i++) {
            vx[i] = Xc[(size_t)i * P];
            vp[i] = pc[(size_t)i * P];
        }
    };
    auto store_gated = [&](int ch, int s) {
        int c0 = ch << 5;
        char* smB = smem + s * FSTG + 32768;
        int b = c0 >> 8;
        float Sp1 = 1.f + Ss[b * 64 + ldrow];
        float val[8];
#pragma unroll
        for (int i = 0; i < 8; i++) {
            int cl = (c0 & 255) + ldq * 8 + i;
            val[i] = vx[i] * (Sp1 + cwsh[b * C + cl]) - vp[i];
        }
#pragma unroll
        for (int g = 0; g < 8; g += 4) {
            int kk = ldq * 8 + g;
            uint32_t h0, l0, h1, l1;
            split2(val[g], val[g + 1], h0, l0);
            split2(val[g + 2], val[g + 3], h1, l1);
            *(uint2*)(smB + swz((uint32_t)(ldrow * 128 + kk * 2))) = make_uint2(h0, h1);
            *(uint2*)(smB + swz((uint32_t)(ldrow * 128 + 64 + kk * 2))) = make_uint2(l0, l1);
        }
    };
    auto loadA = [&](int ch, int s) {
        int c0 = ch << 5;
        uint32_t stA = sb + s * FSTG;
#pragma unroll
        for (int i = 0; i < 8; i++) {
            int idx = i * 256 + tid;
            int row = idx >> 3, slot = idx & 7;
            int til = slot >> 2, q = slot & 3;
            const __nv_bfloat16* srcA =
                (til ? WL : WH) + (size_t)row * KFULL + c0 + q * 8;
            cpasync16(stA + swz((uint32_t)(row * 128 + til * 64 + q * 16)), srcA);
        }
    };
    auto loadB_x = [&](int ch, int s) {
        int c0 = ch << 5;
        uint32_t stB = sb + s * FSTG + 32768;
        int xc0 = c0 - COUT3;
#pragma unroll
        for (int i = 0; i < 2; i++) {
            int idx = i * 256 + tid;
            int row = idx >> 3, slot = idx & 7;
            int til = slot >> 2, q = slot & 3;
            const __nv_bfloat16* srcB =
                (til ? g_xl : g_xh) + ((size_t)n * P + col0 + row) * C + xc0 + q * 8;
            cpasync16(stB + swz((uint32_t)(row * 128 + til * 64 + q * 16)), srcB);
        }
    };

    // prologue: chunks 0 and 1 (both gated since COUT3 > 64 channels)
#pragma unroll
    for (int pre = 0; pre < 2; pre++) {
        loadA(pre, pre);
        if ((pre << 5) < COUT3) { gather_gated(pre); store_gated(pre, pre); }
        else loadB_x(pre, pre);
        cp_commit();
    }

    int s = 0;
    for (int ch = 0; ch < nchunks; ch++) {
        bool pre_gated = (ch + 2 < nchunks) && (((ch + 2) << 5) < COUT3);
        if (pre_gated) gather_gated(ch + 2);   // LDGs overlap the MMA phase
        cp_wait1();
        __syncthreads();
        uint32_t stA = sb + s * FSTG;
        uint32_t stB = stA + 32768;
#pragma unroll
        for (int ks = 0; ks < 2; ks++) {
            int kb = ks * 32;
            uint32_t bH[2][4], bL[2][4];
#pragma unroll
            for (int nip = 0; nip < 2; nip++) {
                int row = warp_n * 32 + nip * 16 + bRowOff;
                ldsm4(bH[nip], stB + swz((uint32_t)(row * 128 + kb + bColOff)));
                ldsm4(bL[nip], stB + swz((uint32_t)(row * 128 + 64 + kb + bColOff)));
            }
#pragma unroll
            for (int mi = 0; mi < 4; mi++) {
                uint32_t aH[4], aL[4];
                int row = warp_m * 64 + mi * 16 + aRowOff;
                ldsm4(aH, stA + swz((uint32_t)(row * 128 + kb + aKOff16)));
                ldsm4(aL, stA + swz((uint32_t)(row * 128 + 64 + kb + aKOff16)));
                mma_block(acc[mi], aH, aL, bH, bL);
            }
        }
        __syncthreads();
        if (ch + 2 < nchunks) {
            loadA(ch + 2, s);
            if (pre_gated) store_gated(ch + 2, s);
            else loadB_x(ch + 2, s);
        }
        cp_commit();
        s ^= 1;
    }

    int r = lane >> 2, q = lane & 3;
#pragma unroll
    for (int mi = 0; mi < 4; mi++) {
        int o = warp_m * 64 + mi * 16 + r;
        float b0 = bias[o];
        float b8 = bias[o + 8];
#pragma unroll
        for (int ni = 0; ni < 4; ni++) {
            int p = col0 + warp_n * 32 + ni * 8 + q * 2;
            size_t i0 = (size_t)o * P + p;
            size_t i1 = (size_t)(o + 8) * P + p;
            *(float2*)&Yn[i0] = make_float2(acc[mi][ni][0] + b0, acc[mi][ni][1] + b0);
            *(float2*)&Yn[i1] = make_float2(acc[mi][ni][2] + b8, acc[mi][ni][3] + b8);
        }
    }
}

// ===== tqred: fused ch_wq logits + exp + per-channel partial reductions =====
__global__ __launch_bounds__(256) void tqred_kernel(const float* __restrict__ wq,
                                                    const float* __restrict__ bq) {
    int b = blockIdx.z, n = blockIdx.y, blk = blockIdx.x;
    int p0 = blk * 128;
    int tid = threadIdx.x;
    __shared__ float wqs[C], Wes[128], wcs[128], part[256];

    wqs[tid] = wq[tid];
    __syncthreads();

    {
        int px = tid & 127, half = tid >> 7;
        const float* Xb = g_expx + ((size_t)n * COUT3 + b * C + half * 128) * P + p0 + px;
        float a0 = 0.f, a1 = 0.f;
#pragma unroll 8
        for (int c = 0; c < 128; c += 2) {
            a0 += wqs[half * 128 + c] * Xb[(size_t)c * P];
            a1 += wqs[half * 128 + c + 1] * Xb[(size_t)(c + 1) * P];
        }
        part[tid] = a0 + a1;
    }
    __syncthreads();
    if (tid < 128) {
        float T = part[tid] + part[tid + 128] + bq[0];
        float w = (b == 2) ? g_wcov[p0 + tid] : 1.f;
        wcs[tid] = w;
        Wes[tid] = w * expf(T);
    }
    __syncthreads();

    if (tid < 32) {
        float z = Wes[tid] + Wes[tid + 32] + Wes[tid + 64] + Wes[tid + 96];
#pragma unroll
        for (int o = 16; o > 0; o >>= 1) z += __shfl_xor_sync(0xffffffffu, z, o);
        if (tid == 0) g_pz[b][n][blk] = z;
    }

    int w = tid >> 5, lane = tid & 31;
#pragma unroll 2
    for (int cc = 0; cc < 32; cc += 2) {
        int c = w * 32 + cc;
        const float* Xc0 = g_expx + ((size_t)n * COUT3 + b * C + c) * P + p0;
        const float* Xc1 = Xc0 + P;
        float xs0 = 0.f, ys0 = 0.f, xs1 = 0.f, ys1 = 0.f;
#pragma unroll
        for (int i = 0; i < 4; i++) {
            int p = lane + i * 32;
            float X0 = Xc0[p], X1 = Xc1[p];
            float wc = wcs[p], we = Wes[p];
            xs0 += wc * X0;
            ys0 += we * X0;
            xs1 += wc * X1;
            ys1 += we * X1;
        }
#pragma unroll
        for (int o = 16; o > 0; o >>= 1) {
            xs0 += __shfl_xor_sync(0xffffffffu, xs0, o);
            ys0 += __shfl_xor_sync(0xffffffffu, ys0, o);
            xs1 += __shfl_xor_sync(0xffffffffu, xs1, o);
            ys1 += __shfl_xor_sync(0xffffffffu, ys1, o);
        }
        if (lane == 0) {
            g_pxs[b][n][blk][c] = xs0;
            g_pys[b][n][blk][c] = ys0;
            g_pxs[b][n][blk][c + 1] = xs1;
            g_pys[b][n][blk][c + 1] = ys1;
        }
    }
}

// =========================== prep kernels ===========================
// wsplit: float4 in, packed 4-bf16 uint2 out (total must be multiple of 4)
__global__ void wsplit_kernel(const float* __restrict__ W,
                              __nv_bfloat16* __restrict__ H,
                              __nv_bfloat16* __restrict__ L, int total) {
    int idx = (blockIdx.x * 256 + threadIdx.x) * 4;
    if (idx < total) {
        float4 v = *(const float4*)&W[idx];
        uint32_t h0, l0, h1, l1;
        split2(v.x, v.y, h0, l0);
        split2(v.z, v.w, h1, l1);
        *(uint2*)&H[idx] = make_uint2(h0, h1);
        *(uint2*)&L[idx] = make_uint2(l0, l1);
    }
}

// xprep: transpose + split, packed 4-bf16 stores (bank-conflict-free)
__global__ __launch_bounds__(256) void xprep_kernel(const float* __restrict__ x) {
    __shared__ float tile[32][33];
    int n = blockIdx.z;
    int p0 = blockIdx.x * 32, c0 = blockIdx.y * 32;
    int tx = threadIdx.x & 31, ty = threadIdx.x >> 5;
    for (int i = ty; i < 32; i += 8)
        tile[i][tx] = x[((size_t)n * C + c0 + i) * P + p0 + tx];
    __syncthreads();
    // store: thread -> pixel p = tid>>3, channel group cg = (tid&7)*4
    int p = threadIdx.x >> 3, cg = (threadIdx.x & 7) * 4;
    float v0 = tile[cg + 0][p], v1 = tile[cg + 1][p];
    float v2 = tile[cg + 2][p], v3 = tile[cg + 3][p];
    uint32_t h0, l0, h1, l1;
    split2(v0, v1, h0, l0);
    split2(v2, v3, h1, l1);
    size_t dst = ((size_t)n * P + p0 + p) * C + c0 + cg;
    *(uint2*)&g_xh[dst] = make_uint2(h0, h1);
    *(uint2*)&g_xl[dst] = make_uint2(l0, l1);
}

// wcat: blocks 0..KFULL-1 build [Wc | Wf] split; block KFULL computes bc.
__global__ __launch_bounds__(256) void wcat_kernel(const float* __restrict__ Wf,
                                                   const float* __restrict__ Wr,
                                                   const float* __restrict__ br,
                                                   const float* __restrict__ bf) {
    int c = blockIdx.x;
    int o = threadIdx.x;
    if (c == KFULL) {
        float a = 0.f;
#pragma unroll 8
        for (int m = 0; m < C; m++) a += Wf[o * C + m] * br[m];
        g_bc[o] = a + bf[o];
        return;
    }
    float a;
    if (c < COUT3) {
        __shared__ float col[C];
        col[o] = Wr[o * COUT3 + c];
        __syncthreads();
        const float* row = Wf + o * C;
        a = 0.f;
#pragma unroll 8
        for (int m = 0; m < C; m++) a += row[m] * col[m];
    } else {
        a = Wf[o * C + (c - COUT3)];
    }
    __nv_bfloat16 h = __float2bfloat16_rn(a);
    g_WcatH[o * KFULL + c] = h;
    g_WcatL[o * KFULL + c] = __float2bfloat16_rn(a - __bfloat162float(h));
}

// =========================== non-GEMM kernels ===========================
__device__ __forceinline__ int cov6(int h) {
    int r = 0;
#pragma unroll
    for (int j = 0; j < 6; j++) r += (h >= 10 * j) && (h <= 10 * j + 13);
    return r;
}
__device__ __forceinline__ float sigmoidf_(float x) { return 1.0f / (1.0f + expf(-x)); }

__global__ void pos_kernel() {
    int idx = blockIdx.x * blockDim.x + threadIdx.x;  // < C*P
    int prow = idx >> 8;
    int c = idx & 255;
    int i = prow >> 6;
    int j = prow & 63;
    int k = c & 63;
    // 10000^(-k/64) = exp2(-k * log2(10000)/64)
    float omega = exp2f((float)k * -0.2076245786f);
    float coord = (c < 128) ? (float)i : (float)j;
    float a = coord * omega;
    float val = ((c >> 6) & 1) ? cosf(a) : sinf(a);
    g_pos[idx] = val;
    if (idx < P) {
        int h = idx >> 6, w = idx & 63;
        g_wcov[idx] = (float)(cov6(h) * cov6(w));
    }
}

// tiny: folds the 32 per-block partials itself
__global__ __launch_bounds__(256) void tiny_kernel(
    const float* __restrict__ Wv, const float* __restrict__ bv,
    const float* __restrict__ Wz, const float* __restrict__ bz,
    const float* __restrict__ lg, const float* __restrict__ lb,
    const float* __restrict__ Wqs, const float* __restrict__ bqs,
    const float* __restrict__ Wvs, const float* __restrict__ bvs)
{
    int n = blockIdx.x, b = blockIdx.y;
    __shared__ float y[C], xb[C], zz[C2], sq[C2], wzs[C], red[256];
    int t = threadIdx.x;
    float L = (b == 2) ? 7056.f : 4096.f;

    float xs = 0.f, ys = 0.f;
#pragma unroll
    for (int k = 0; k < 32; k++) {
        xs += g_pxs[b][n][k][t];
        ys += g_pys[b][n][k][t];
    }
    float Zn = 0.f;
#pragma unroll
    for (int k = 0; k < 32; k++) Zn += g_pz[b][n][k];

    y[t] = ys / Zn;
    xb[t] = xs / L;
    __syncthreads();

    if (t < C2) {
        float a = 0.f;
        for (int c = 0; c < C; c++) a += Wv[t * C + c] * y[c];
        zz[t] = a + bv[t];
    }
    __syncthreads();

    {
        float a = 0.f;
        for (int c2 = 0; c2 < C2; c2++) a += Wz[t * C2 + c2] * zz[c2];
        wzs[t] = a + bz[t];
    }
    __syncthreads();

    red[t] = wzs[t]; __syncthreads();
    for (int s = 128; s > 0; s >>= 1) { if (t < s) red[t] += red[t + s]; __syncthreads(); }
    float m = red[0] / 256.f; __syncthreads();
    float d = wzs[t] - m;
    red[t] = d * d; __syncthreads();
    for (int s = 128; s > 0; s >>= 1) { if (t < s) red[t] += red[t + s]; __syncthreads(); }
    float var = red[0] / 256.f; __syncthreads();
    g_chw[b][n * C + t] = sigmoidf_(d * rsqrtf(var + 1e-5f) * lg[t] + lb[t]);

    if (t < C2) {
        float a = 0.f;
        for (int c = 0; c < C; c++) a += Wqs[t * C + c] * xb[c];
        zz[t] = a + bqs[t];
    }
    __syncthreads();
    red[t] = (t < C2) ? zz[t] : -1e30f; __syncthreads();
    for (int s = 128; s > 0; s >>= 1) { if (t < s) red[t] = fmaxf(red[t], red[t + s]); __syncthreads(); }
    float mx = red[0]; __syncthreads();
    float e = (t < C2) ? expf(zz[t] - mx) : 0.f;
    if (t < C2) sq[t] = e;
    red[t] = e; __syncthreads();
    for (int s = 128; s > 0; s >>= 1) { if (t < s) red[t] += red[t + s]; __syncthreads(); }
    float se = red[0]; __syncthreads();
    if (t < C2) sq[t] /= se;
    __syncthreads();

    {
        float a = 0.f;
        for (int c2 = 0; c2 < C2; c2++) a += sq[c2] * Wvs[c2 * C + t];
        g_v[b][n * C + t] = a;
    }
    red[t] = (t < C2) ? sq[t] * bvs[t] : 0.f; __syncthreads();
    for (int s = 128; s > 0; s >>= 1) { if (t < s) red[t] += red[t + s]; __syncthreads(); }
    if (t == 0) g_beta[b][n] = red[0];
}

// ---------------- host ----------------
extern "C" void kernel_launch(void* const* d_in, const int* in_sizes, int n_in,
                              void* d_out, int out_size) {
    const float* x       = (const float*)d_in[0];
    const float* w_exp   = (const float*)d_in[1];
    const float* b_exp   = (const float*)d_in[2];
    const float* w_res   = (const float*)d_in[3];
    const float* b_res   = (const float*)d_in[4];
    const float* w_fus   = (const float*)d_in[5];
    const float* b_fus   = (const float*)d_in[6];
    const float* ch_wv_w = (const float*)d_in[7];
    const float* ch_wv_b = (const float*)d_in[8];
    const float* ch_wq_w = (const float*)d_in[9];
    const float* ch_wq_b = (const float*)d_in[10];
    const float* ch_wz_w = (const float*)d_in[11];
    const float* ch_wz_b = (const float*)d_in[12];
    const float* ln_g    = (const float*)d_in[13];
    const float* ln_b    = (const float*)d_in[14];
    const float* sp_wv_w = (const float*)d_in[15];
    const float* sp_wv_b = (const float*)d_in[16];
    const float* sp_wq_w = (const float*)d_in[17];
    const float* sp_wq_b = (const float*)d_in[18];

    float *p_expx, *p_bc, *p_pos;
    __nv_bfloat16 *p_WexpH, *p_WexpL, *p_WcatH, *p_WcatL;
    cudaGetSymbolAddress((void**)&p_expx, g_expx);
    cudaGetSymbolAddress((void**)&p_bc, g_bc);
    cudaGetSymbolAddress((void**)&p_pos, g_pos);
    cudaGetSymbolAddress((void**)&p_WexpH, g_WexpH);
    cudaGetSymbolAddress((void**)&p_WexpL, g_WexpL);
    cudaGetSymbolAddress((void**)&p_WcatH, g_WcatH);
    cudaGetSymbolAddress((void**)&p_WcatL, g_WcatL);

    cudaFuncSetAttribute(gemm_mma4,
                         cudaFuncAttributeMaxDynamicSharedMemorySize, SM_BYTES);
    cudaFuncSetAttribute(gemm_fin,
                         cudaFuncAttributeMaxDynamicSharedMemorySize, FSM_BYTES);

    pos_kernel<<<(C * P) / 256, 256>>>();
    wcat_kernel<<<KFULL + 1, 256>>>(w_fus, w_res, b_res, b_fus);
    wsplit_kernel<<<(COUT3 * C) / 1024, 256>>>(w_exp, p_WexpH, p_WexpL, COUT3 * C);
    xprep_kernel<<<dim3(P / 32, C / 32, NB), 256>>>(x);

    // g_expx = X = W_exp @ x + b_exp + pos  (pos fused in epilogue)
    gemm_mma4<<<dim3(P / 128, COUT3 / 128, NB), 256, SM_BYTES>>>(
        p_WexpH, p_WexpL, b_exp, p_expx, C, COUT3, p_pos);

    tqred_kernel<<<dim3(P / 128, NB, 3), 256>>>(ch_wq_w, ch_wq_b);
    tiny_kernel<<<dim3(NB, 3), 256>>>(ch_wv_w, ch_wv_b, ch_wz_w, ch_wz_b,
                                      ln_g, ln_b, sp_wq_w, sp_wq_b,
                                      sp_wv_w, sp_wv_b);

    // out = [Wc | W_fus] @ [gated-cat ; x] + bc   (prefetched gated loader)
    gemm_fin<<<dim3(P / 64, 1, NB), 256, FSM_BYTES>>>(
        p_WcatH, p_WcatL, p_bc, (float*)d_out);
}

// round 17
// speedup vs baseline: 1.0800x; 1.0210x over previous
#include <cuda_runtime.h>
#include <cuda_bf16.h>
#include <math.h>
#include <stdint.h>

#define NB 8
#define C 256
#define C2 128
#define P 4096          // 64*64 pixels
#define COUT3 768
#define KFULL 1024      // 768 gated channels + 256 raw x channels

// ---------------- scratch (device globals; no allocs allowed) ----------------
__device__ float g_pos[C * P];                 // positional encoding, 4 MB
__device__ float g_expx[NB * COUT3 * P];       // X = expx + pos (stored fused)
__device__ float g_wcov[P];                    // coverage weights for win=6
__device__ float g_chw[3][NB * C];             // channel gate
__device__ float g_v[3][NB * C];               // spatial-gate projection vector
__device__ float g_beta[3][NB];                // spatial-gate bias
__device__ float g_bc[C];                      // W_fus @ b_res + b_fus
// per-block partials for the fused tq+red reduction (P/128 = 32 blocks)
__device__ float g_pxs[3][NB][32][C];
__device__ float g_pys[3][NB][32][C];
__device__ float g_pz[3][NB][32];

// pre-split operands (bf16 hi/lo)
__device__ __nv_bfloat16 g_WexpH[COUT3 * C], g_WexpL[COUT3 * C];
__device__ __nv_bfloat16 g_WcatH[C * KFULL], g_WcatL[C * KFULL];
__device__ __nv_bfloat16 g_xh[NB * P * C], g_xl[NB * P * C];   // [n][p][c]

// ================= helpers =================
__device__ __forceinline__ uint32_t smem_u32(const void* p) {
    uint32_t a;
    asm("{ .reg .u64 t; cvta.to.shared.u64 t, %1; cvt.u32.u64 %0, t; }"
        : "=r"(a) : "l"(p));
    return a;
}
__device__ __forceinline__ uint32_t swz(uint32_t b) { return b ^ ((b >> 3) & 0x70); }

__device__ __forceinline__ void split2(float a, float b, uint32_t& hp, uint32_t& lp) {
    __nv_bfloat16 ha = __float2bfloat16_rn(a);
    __nv_bfloat16 hb = __float2bfloat16_rn(b);
    __nv_bfloat16 la = __float2bfloat16_rn(a - __bfloat162float(ha));
    __nv_bfloat16 lb = __float2bfloat16_rn(b - __bfloat162float(hb));
    hp = (uint32_t)__bfloat16_as_ushort(ha) | ((uint32_t)__bfloat16_as_ushort(hb) << 16);
    lp = (uint32_t)__bfloat16_as_ushort(la) | ((uint32_t)__bfloat16_as_ushort(lb) << 16);
}

__device__ __forceinline__ void ldsm4(uint32_t a[4], uint32_t addr) {
    asm volatile("ldmatrix.sync.aligned.m8n8.x4.shared.b16 {%0,%1,%2,%3}, [%4];"
                 : "=r"(a[0]), "=r"(a[1]), "=r"(a[2]), "=r"(a[3]) : "r"(addr));
}
__device__ __forceinline__ void mma16816(float d[4], const uint32_t a[4],
                                         const uint32_t b0, const uint32_t b1) {
    asm("mma.sync.aligned.m16n8k16.row.col.f32.bf16.bf16.f32 "
        "{%0,%1,%2,%3}, {%4,%5,%6,%7}, {%8,%9}, {%0,%1,%2,%3};"
        : "+f"(d[0]), "+f"(d[1]), "+f"(d[2]), "+f"(d[3])
        : "r"(a[0]), "r"(a[1]), "r"(a[2]), "r"(a[3]), "r"(b0), "r"(b1));
}
__device__ __forceinline__ void cpasync16(uint32_t dst, const void* src) {
    asm volatile("cp.async.ca.shared.global [%0], [%1], 16;" :: "r"(dst), "l"(src));
}
__device__ __forceinline__ void cp_commit() {
    asm volatile("cp.async.commit_group;" ::: "memory");
}
__device__ __forceinline__ void cp_wait1() {
    asm volatile("cp.async.wait_group 1;" ::: "memory");
}

// 12 MMAs for one A hi/lo pair against both B nip-halves.
__device__ __forceinline__ void mma_block(float acc[4][4],
                                          const uint32_t aH[4], const uint32_t aL[4],
                                          const uint32_t bH[2][4], const uint32_t bL[2][4]) {
    mma16816(acc[0], aH, bH[0][0], bH[0][1]);
    mma16816(acc[1], aH, bH[0][2], bH[0][3]);
    mma16816(acc[2], aH, bH[1][0], bH[1][1]);
    mma16816(acc[3], aH, bH[1][2], bH[1][3]);
    mma16816(acc[0], aH, bL[0][0], bL[0][1]);
    mma16816(acc[1], aH, bL[0][2], bL[0][3]);
    mma16816(acc[2], aH, bL[1][0], bL[1][1]);
    mma16816(acc[3], aH, bL[1][2], bL[1][3]);
    mma16816(acc[0], aL, bH[0][0], bH[0][1]);
    mma16816(acc[1], aL, bH[0][2], bH[0][3]);
    mma16816(acc[2], aL, bH[1][0], bH[1][1]);
    mma16816(acc[3], aL, bH[1][2], bH[1][3]);
}

// ======= GEMM1 (expx): Y[n,o,p] = sum_c A[o,c] B[c,p] + bias (+pos) =======
// 3-slot ring, ONE __syncthreads per chunk.
#define STG 32768
#define SM_BYTES (3 * STG)

__global__ void __launch_bounds__(256, 2)
gemm_mma4(const __nv_bfloat16* __restrict__ WH, const __nv_bfloat16* __restrict__ WL,
          const float* __restrict__ bias, float* __restrict__ Y,
          int Cin, int Cout, const float* __restrict__ pos_add)
{
    extern __shared__ char smem[];
    uint32_t sb = smem_u32(smem);
    int tid = threadIdx.x, wid = tid >> 5, lane = tid & 31;
    int n = blockIdx.z;
    int row0 = blockIdx.y * 128, col0 = blockIdx.x * 128;
    float* Yn = Y + (size_t)n * Cout * P;

    int warp_m = wid >> 2;
    int warp_n = wid & 3;

    float acc[4][4][4];
#pragma unroll
    for (int i = 0; i < 4; i++)
#pragma unroll
        for (int j = 0; j < 4; j++)
#pragma unroll
            for (int k = 0; k < 4; k++) acc[i][j][k] = 0.f;

    int l7 = lane & 7;
    int aRowOff = ((lane >> 3) & 1) * 8 + l7;
    int aKOff16 = (lane >> 4) * 16;
    int bRowOff = ((lane >> 4) & 1) * 8 + l7;
    int bColOff = ((lane >> 3) & 1) * 16;

    int nchunks = Cin >> 5;

    auto load_stage = [&](int ch, int s) {
        int c0 = ch << 5;
        uint32_t stA = sb + s * STG;
        uint32_t stB = stA + 16384;
#pragma unroll
        for (int i = 0; i < 4; i++) {
            int idx = i * 256 + tid;
            int row = idx >> 3, slot = idx & 7;
            int til = slot >> 2, q = slot & 3;
            const __nv_bfloat16* srcA =
                (til ? WL : WH) + (size_t)(row0 + row) * Cin + c0 + q * 8;
            cpasync16(stA + swz((uint32_t)(row * 128 + til * 64 + q * 16)), srcA);
            const __nv_bfloat16* srcB =
                (til ? g_xl : g_xh) + ((size_t)n * P + col0 + row) * C + c0 + q * 8;
            cpasync16(stB + swz((uint32_t)(row * 128 + til * 64 + q * 16)), srcB);
        }
    };

    load_stage(0, 0);
    cp_commit();

    for (int ch = 0; ch < nchunks; ch++) {
        if (ch + 1 < nchunks) load_stage(ch + 1, (ch + 1) % 3);
        cp_commit();
        cp_wait1();
        __syncthreads();
        uint32_t stA = sb + (ch % 3) * STG;
        uint32_t stB = stA + 16384;
#pragma unroll
        for (int ks = 0; ks < 2; ks++) {
            int kb = ks * 32;
            uint32_t bH[2][4], bL[2][4];
#pragma unroll
            for (int nip = 0; nip < 2; nip++) {
                int row = warp_n * 32 + nip * 16 + bRowOff;
                ldsm4(bH[nip], stB + swz((uint32_t)(row * 128 + kb + bColOff)));
                ldsm4(bL[nip], stB + swz((uint32_t)(row * 128 + 64 + kb + bColOff)));
            }
#pragma unroll
            for (int mi = 0; mi < 4; mi++) {
                uint32_t aH[4], aL[4];
                int row = warp_m * 64 + mi * 16 + aRowOff;
                ldsm4(aH, stA + swz((uint32_t)(row * 128 + kb + aKOff16)));
                ldsm4(aL, stA + swz((uint32_t)(row * 128 + 64 + kb + aKOff16)));
                mma_block(acc[mi], aH, aL, bH, bL);
            }
        }
    }

    int r = lane >> 2, q = lane & 3;
#pragma unroll
    for (int mi = 0; mi < 4; mi++) {
        int o = row0 + warp_m * 64 + mi * 16 + r;
        float b0 = bias[o];
        float b8 = bias[o + 8];
#pragma unroll
        for (int ni = 0; ni < 4; ni++) {
            int p = col0 + warp_n * 32 + ni * 8 + q * 2;
            size_t i0 = (size_t)o * P + p;
            size_t i1 = (size_t)(o + 8) * P + p;
            float2 v0 = make_float2(acc[mi][ni][0] + b0, acc[mi][ni][1] + b0);
            float2 v1 = make_float2(acc[mi][ni][2] + b8, acc[mi][ni][3] + b8);
            if (pos_add) {
                size_t q0 = (size_t)(o & 255) * P + p;
                size_t q1 = (size_t)((o + 8) & 255) * P + p;
                float2 p0 = *(const float2*)&pos_add[q0];
                float2 p1 = *(const float2*)&pos_add[q1];
                v0.x += p0.x; v0.y += p0.y;
                v1.x += p1.x; v1.y += p1.y;
            }
            *(float2*)&Yn[i0] = v0;
            *(float2*)&Yn[i1] = v1;
        }
    }
}

// ======= GEMM2 (final): M=256 x N=128, 512 thr, 3-slot single-barrier ring ====
#define FSTG2 49152           // A 32 KB + B 16 KB
#define FSM_BYTES (3 * FSTG2)

__global__ void __launch_bounds__(512, 1)
gemm_fin(const __nv_bfloat16* __restrict__ WH, const __nv_bfloat16* __restrict__ WL,
         const float* __restrict__ bias, float* __restrict__ Y)
{
    extern __shared__ char smem[];
    __shared__ float vsh[3 * C];
    __shared__ float cwsh[3 * C];
    __shared__ float redp[512];
    __shared__ float Ss[3 * 128];
    uint32_t sb = smem_u32(smem);
    int tid = threadIdx.x, wid = tid >> 5, lane = tid & 31;
    int n = blockIdx.z;
    int col0 = blockIdx.x * 128;
    float* Yn = Y + (size_t)n * C * P;

    // ---- prologue: load v + chw, compute S for this CTA's 128 pixels ----
    for (int i = tid; i < 3 * C; i += 512) {
        int b = i >> 8, c = i & 255;
        vsh[i] = g_v[b][n * C + c];
        cwsh[i] = g_chw[b][n * C + c];
    }
    __syncthreads();
    {
        int px = tid & 127, sq = tid >> 7;   // 4 quarters of 64 channels
#pragma unroll 1
        for (int b = 0; b < 3; b++) {
            const float* Xb = g_expx + ((size_t)n * COUT3 + b * C + sq * 64) * P + col0 + px;
            float a = 0.f;
#pragma unroll 8
            for (int c = 0; c < 64; c++) a += vsh[b * C + sq * 64 + c] * Xb[(size_t)c * P];
            redp[tid] = a;
            __syncthreads();
            if (tid < 128)
                Ss[b * 128 + tid] = 1.f / (1.f + expf(-(redp[tid] + redp[tid + 128] +
                                                       redp[tid + 256] + redp[tid + 384] +
                                                       g_beta[b][n])));
            __syncthreads();
        }
    }

    int warp_m = wid >> 2;   // 0..3 -> 64 rows each (M=256)
    int warp_n = wid & 3;    // 0..3 -> 32 cols (N=128)

    float acc[4][4][4];
#pragma unroll
    for (int i = 0; i < 4; i++)
#pragma unroll
        for (int j = 0; j < 4; j++)
#pragma unroll
            for (int k = 0; k < 4; k++) acc[i][j][k] = 0.f;

    int l7 = lane & 7;
    int aRowOff = ((lane >> 3) & 1) * 8 + l7;
    int aKOff16 = (lane >> 4) * 16;
    int bRowOff = ((lane >> 4) & 1) * 8 + l7;
    int bColOff = ((lane >> 3) & 1) * 16;

    const int nchunks = KFULL >> 5;   // 32
    int ldrow = tid & 127, ldq = tid >> 7;   // pixel, quarter (8 channels)
    int pg = col0 + ldrow;

    float vx[8], vp[8];
    auto gather_gated = [&](int ch) {
        int c0 = ch << 5;
        const float* Xc = &g_expx[((size_t)n * COUT3 + c0 + ldq * 8) * P + pg];
        const float* pc = &g_pos[(size_t)((c0 & 255) + ldq * 8) * P + pg];
#pragma unroll
        for (int i = 0; i < 8; i++) {
            vx[i] = Xc[(size_t)i * P];
            vp[i] = pc[(size_t)i * P];
        }
    };
    auto store_gated = [&](int ch, int s) {
        int c0 = ch << 5;
        char* smB = smem + s * FSTG2 + 32768;
        int b = c0 >> 8;
        float Sp1 = 1.f + Ss[b * 128 + ldrow];
        float val[8];
#pragma unroll
        for (int i = 0; i < 8; i++) {
            int cl = (c0 & 255) + ldq * 8 + i;
            val[i] = vx[i] * (Sp1 + cwsh[b * C + cl]) - vp[i];
        }
#pragma unroll
        for (int g = 0; g < 8; g += 4) {
            int kk = ldq * 8 + g;
            uint32_t h0, l0, h1, l1;
            split2(val[g], val[g + 1], h0, l0);
            split2(val[g + 2], val[g + 3], h1, l1);
            *(uint2*)(smB + swz((uint32_t)(ldrow * 128 + kk * 2))) = make_uint2(h0, h1);
            *(uint2*)(smB + swz((uint32_t)(ldrow * 128 + 64 + kk * 2))) = make_uint2(l0, l1);
        }
    };
    auto loadA = [&](int ch, int s) {
        int c0 = ch << 5;
        uint32_t stA = sb + s * FSTG2;
#pragma unroll
        for (int i = 0; i < 4; i++) {
            int idx = i * 512 + tid;
            int row = idx >> 3, slot = idx & 7;
            int til = slot >> 2, q = slot & 3;
            const __nv_bfloat16* srcA =
                (til ? WL : WH) + (size_t)row * KFULL + c0 + q * 8;
            cpasync16(stA + swz((uint32_t)(row * 128 + til * 64 + q * 16)), srcA);
        }
    };
    auto loadB_x = [&](int ch, int s) {
        int c0 = ch << 5;
        uint32_t stB = sb + s * FSTG2 + 32768;
        int xc0 = c0 - COUT3;
#pragma unroll
        for (int i = 0; i < 2; i++) {
            int idx = i * 512 + tid;
            int row = idx >> 3, slot = idx & 7;
            int til = slot >> 2, q = slot & 3;
            const __nv_bfloat16* srcB =
                (til ? g_xl : g_xh) + ((size_t)n * P + col0 + row) * C + xc0 + q * 8;
            cpasync16(stB + swz((uint32_t)(row * 128 + til * 64 + q * 16)), srcB);
        }
    };

    // prologue: chunk 0 into slot 0; pre-gather chunk 1
    gather_gated(0);
    loadA(0, 0);
    store_gated(0, 0);
    cp_commit();
    gather_gated(1);

    for (int ch = 0; ch < nchunks; ch++) {
        if (ch + 1 < nchunks) {
            int s1 = (ch + 1) % 3;
            loadA(ch + 1, s1);
            if (((ch + 1) << 5) < COUT3) store_gated(ch + 1, s1);
            else loadB_x(ch + 1, s1);
        }
        if (ch + 2 < nchunks && (((ch + 2) << 5) < COUT3)) gather_gated(ch + 2);
        cp_commit();
        cp_wait1();
        __syncthreads();
        uint32_t stA = sb + (ch % 3) * FSTG2;
        uint32_t stB = stA + 32768;
#pragma unroll
        for (int ks = 0; ks < 2; ks++) {
            int kb = ks * 32;
            uint32_t bH[2][4], bL[2][4];
#pragma unroll
            for (int nip = 0; nip < 2; nip++) {
                int row = warp_n * 32 + nip * 16 + bRowOff;
                ldsm4(bH[nip], stB + swz((uint32_t)(row * 128 + kb + bColOff)));
                ldsm4(bL[nip], stB + swz((uint32_t)(row * 128 + 64 + kb + bColOff)));
            }
#pragma unroll
            for (int mi = 0; mi < 4; mi++) {
                uint32_t aH[4], aL[4];
                int row = warp_m * 64 + mi * 16 + aRowOff;
                ldsm4(aH, stA + swz((uint32_t)(row * 128 + kb + aKOff16)));
                ldsm4(aL, stA + swz((uint32_t)(row * 128 + 64 + kb + aKOff16)));
                mma_block(acc[mi], aH, aL, bH, bL);
            }
        }
    }

    int r = lane >> 2, q = lane & 3;
#pragma unroll
    for (int mi = 0; mi < 4; mi++) {
        int o = warp_m * 64 + mi * 16 + r;
        float b0 = bias[o];
        float b8 = bias[o + 8];
#pragma unroll
        for (int ni = 0; ni < 4; ni++) {
            int p = col0 + warp_n * 32 + ni * 8 + q * 2;
            size_t i0 = (size_t)o * P + p;
            size_t i1 = (size_t)(o + 8) * P + p;
            *(float2*)&Yn[i0] = make_float2(acc[mi][ni][0] + b0, acc[mi][ni][1] + b0);
            *(float2*)&Yn[i1] = make_float2(acc[mi][ni][2] + b8, acc[mi][ni][3] + b8);
        }
    }
}

// ===== tqred: fused ch_wq logits + exp + per-channel partial reductions =====
__global__ __launch_bounds__(256) void tqred_kernel(const float* __restrict__ wq,
                                                    const float* __restrict__ bq) {
    int b = blockIdx.z, n = blockIdx.y, blk = blockIdx.x;
    int p0 = blk * 128;
    int tid = threadIdx.x;
    __shared__ float wqs[C], Wes[128], wcs[128], part[256];

    wqs[tid] = wq[tid];
    __syncthreads();

    {
        int px = tid & 127, half = tid >> 7;
        const float* Xb = g_expx + ((size_t)n * COUT3 + b * C + half * 128) * P + p0 + px;
        float a0 = 0.f, a1 = 0.f;
#pragma unroll 8
        for (int c = 0; c < 128; c += 2) {
            a0 += wqs[half * 128 + c] * Xb[(size_t)c * P];
            a1 += wqs[half * 128 + c + 1] * Xb[(size_t)(c + 1) * P];
        }
        part[tid] = a0 + a1;
    }
    __syncthreads();
    if (tid < 128) {
        float T = part[tid] + part[tid + 128] + bq[0];
        float w = (b == 2) ? g_wcov[p0 + tid] : 1.f;
        wcs[tid] = w;
        Wes[tid] = w * expf(T);
    }
    __syncthreads();

    if (tid < 32) {
        float z = Wes[tid] + Wes[tid + 32] + Wes[tid + 64] + Wes[tid + 96];
#pragma unroll
        for (int o = 16; o > 0; o >>= 1) z += __shfl_xor_sync(0xffffffffu, z, o);
        if (tid == 0) g_pz[b][n][blk] = z;
    }

    int w = tid >> 5, lane = tid & 31;
#pragma unroll 2
    for (int cc = 0; cc < 32; cc += 2) {
        int c = w * 32 + cc;
        const float* Xc0 = g_expx + ((size_t)n * COUT3 + b * C + c) * P + p0;
        const float* Xc1 = Xc0 + P;
        float xs0 = 0.f, ys0 = 0.f, xs1 = 0.f, ys1 = 0.f;
#pragma unroll
        for (int i = 0; i < 4; i++) {
            int p = lane + i * 32;
            float X0 = Xc0[p], X1 = Xc1[p];
            float wc = wcs[p], we = Wes[p];
            xs0 += wc * X0;
            ys0 += we * X0;
            xs1 += wc * X1;
            ys1 += we * X1;
        }
#pragma unroll
        for (int o = 16; o > 0; o >>= 1) {
            xs0 += __shfl_xor_sync(0xffffffffu, xs0, o);
            ys0 += __shfl_xor_sync(0xffffffffu, ys0, o);
            xs1 += __shfl_xor_sync(0xffffffffu, xs1, o);
            ys1 += __shfl_xor_sync(0xffffffffu, ys1, o);
        }
        if (lane == 0) {
            g_pxs[b][n][blk][c] = xs0;
            g_pys[b][n][blk][c] = ys0;
            g_pxs[b][n][blk][c + 1] = xs1;
            g_pys[b][n][blk][c + 1] = ys1;
        }
    }
}

// =========================== prep kernels ===========================
__global__ void wsplit_kernel(const float* __restrict__ W,
                              __nv_bfloat16* __restrict__ H,
                              __nv_bfloat16* __restrict__ L, int total) {
    int idx = (blockIdx.x * 256 + threadIdx.x) * 4;
    if (idx < total) {
        float4 v = *(const float4*)&W[idx];
        uint32_t h0, l0, h1, l1;
        split2(v.x, v.y, h0, l0);
        split2(v.z, v.w, h1, l1);
        *(uint2*)&H[idx] = make_uint2(h0, h1);
        *(uint2*)&L[idx] = make_uint2(l0, l1);
    }
}

__global__ __launch_bounds__(256) void xprep_kernel(const float* __restrict__ x) {
    __shared__ float tile[32][33];
    int n = blockIdx.z;
    int p0 = blockIdx.x * 32, c0 = blockIdx.y * 32;
    int tx = threadIdx.x & 31, ty = threadIdx.x >> 5;
    for (int i = ty; i < 32; i += 8)
        tile[i][tx] = x[((size_t)n * C + c0 + i) * P + p0 + tx];
    __syncthreads();
    int p = threadIdx.x >> 3, cg = (threadIdx.x & 7) * 4;
    float v0 = tile[cg + 0][p], v1 = tile[cg + 1][p];
    float v2 = tile[cg + 2][p], v3 = tile[cg + 3][p];
    uint32_t h0, l0, h1, l1;
    split2(v0, v1, h0, l0);
    split2(v2, v3, h1, l1);
    size_t dst = ((size_t)n * P + p0 + p) * C + c0 + cg;
    *(uint2*)&g_xh[dst] = make_uint2(h0, h1);
    *(uint2*)&g_xl[dst] = make_uint2(l0, l1);
}

__global__ __launch_bounds__(256) void wcat_kernel(const float* __restrict__ Wf,
                                                   const float* __restrict__ Wr,
                                                   const float* __restrict__ br,
                                                   const float* __restrict__ bf) {
    int c = blockIdx.x;
    int o = threadIdx.x;
    if (c == KFULL) {
        float a = 0.f;
#pragma unroll 8
        for (int m = 0; m < C; m++) a += Wf[o * C + m] * br[m];
        g_bc[o] = a + bf[o];
        return;
    }
    float a;
    if (c < COUT3) {
        __shared__ float col[C];
        col[o] = Wr[o * COUT3 + c];
        __syncthreads();
        const float* row = Wf + o * C;
        a = 0.f;
#pragma unroll 8
        for (int m = 0; m < C; m++) a += row[m] * col[m];
    } else {
        a = Wf[o * C + (c - COUT3)];
    }
    __nv_bfloat16 h = __float2bfloat16_rn(a);
    g_WcatH[o * KFULL + c] = h;
    g_WcatL[o * KFULL + c] = __float2bfloat16_rn(a - __bfloat162float(h));
}

// =========================== non-GEMM kernels ===========================
__device__ __forceinline__ int cov6(int h) {
    int r = 0;
#pragma unroll
    for (int j = 0; j < 6; j++) r += (h >= 10 * j) && (h <= 10 * j + 13);
    return r;
}
__device__ __forceinline__ float sigmoidf_(float x) { return 1.0f / (1.0f + expf(-x)); }

__global__ void pos_kernel() {
    int idx = blockIdx.x * blockDim.x + threadIdx.x;  // < C*P
    int prow = idx >> 8;
    int c = idx & 255;
    int i = prow >> 6;
    int j = prow & 63;
    int k = c & 63;
    float omega = exp2f((float)k * -0.2076245786f);
    float coord = (c < 128) ? (float)i : (float)j;
    float a = coord * omega;
    float val = ((c >> 6) & 1) ? cosf(a) : sinf(a);
    g_pos[idx] = val;
    if (idx < P) {
        int h = idx >> 6, w = idx & 63;
        g_wcov[idx] = (float)(cov6(h) * cov6(w));
    }
}

// tiny: folds the 32 per-block partials itself
__global__ __launch_bounds__(256) void tiny_kernel(
    const float* __restrict__ Wv, const float* __restrict__ bv,
    const float* __restrict__ Wz, const float* __restrict__ bz,
    const float* __restrict__ lg, const float* __restrict__ lb,
    const float* __restrict__ Wqs, const float* __restrict__ bqs,
    const float* __restrict__ Wvs, const float* __restrict__ bvs)
{
    int n = blockIdx.x, b = blockIdx.y;
    __shared__ float y[C], xb[C], zz[C2], sq[C2], wzs[C], red[256];
    int t = threadIdx.x;
    float L = (b == 2) ? 7056.f : 4096.f;

    float xs = 0.f, ys = 0.f;
#pragma unroll
    for (int k = 0; k < 32; k++) {
        xs += g_pxs[b][n][k][t];
        ys += g_pys[b][n][k][t];
    }
    float Zn = 0.f;
#pragma unroll
    for (int k = 0; k < 32; k++) Zn += g_pz[b][n][k];

    y[t] = ys / Zn;
    xb[t] = xs / L;
    __syncthreads();

    if (t < C2) {
        float a = 0.f;
        for (int c = 0; c < C; c++) a += Wv[t * C + c] * y[c];
        zz[t] = a + bv[t];
    }
    __syncthreads();

    {
        float a = 0.f;
        for (int c2 = 0; c2 < C2; c2++) a += Wz[t * C2 + c2] * zz[c2];
        wzs[t] = a + bz[t];
    }
    __syncthreads();

    red[t] = wzs[t]; __syncthreads();
    for (int s = 128; s > 0; s >>= 1) { if (t < s) red[t] += red[t + s]; __syncthreads(); }
    float m = red[0] / 256.f; __syncthreads();
    float d = wzs[t] - m;
    red[t] = d * d; __syncthreads();
    for (int s = 128; s > 0; s >>= 1) { if (t < s) red[t] += red[t + s]; __syncthreads(); }
    float var = red[0] / 256.f; __syncthreads();
    g_chw[b][n * C + t] = sigmoidf_(d * rsqrtf(var + 1e-5f) * lg[t] + lb[t]);

    if (t < C2) {
        float a = 0.f;
        for (int c = 0; c < C; c++) a += Wqs[t * C + c] * xb[c];
        zz[t] = a + bqs[t];
    }
    __syncthreads();
    red[t] = (t < C2) ? zz[t] : -1e30f; __syncthreads();
    for (int s = 128; s > 0; s >>= 1) { if (t < s) red[t] = fmaxf(red[t], red[t + s]); __syncthreads(); }
    float mx = red[0]; __syncthreads();
    float e = (t < C2) ? expf(zz[t] - mx) : 0.f;
    if (t < C2) sq[t] = e;
    red[t] = e; __syncthreads();
    for (int s = 128; s > 0; s >>= 1) { if (t < s) red[t] += red[t + s]; __syncthreads(); }
    float se = red[0]; __syncthreads();
    if (t < C2) sq[t] /= se;
    __syncthreads();

    {
        float a = 0.f;
        for (int c2 = 0; c2 < C2; c2++) a += sq[c2] * Wvs[c2 * C + t];
        g_v[b][n * C + t] = a;
    }
    red[t] = (t < C2) ? sq[t] * bvs[t] : 0.f; __syncthreads();
    for (int s = 128; s > 0; s >>= 1) { if (t < s) red[t] += red[t + s]; __syncthreads(); }
    if (t == 0) g_beta[b][n] = red[0];
}

// ---------------- host ----------------
extern "C" void kernel_launch(void* const* d_in, const int* in_sizes, int n_in,
                              void* d_out, int out_size) {
    const float* x       = (const float*)d_in[0];
    const float* w_exp   = (const float*)d_in[1];
    const float* b_exp   = (const float*)d_in[2];
    const float* w_res   = (const float*)d_in[3];
    const float* b_res   = (const float*)d_in[4];
    const float* w_fus   = (const float*)d_in[5];
    const float* b_fus   = (const float*)d_in[6];
    const float* ch_wv_w = (const float*)d_in[7];
    const float* ch_wv_b = (const float*)d_in[8];
    const float* ch_wq_w = (const float*)d_in[9];
    const float* ch_wq_b = (const float*)d_in[10];
    const float* ch_wz_w = (const float*)d_in[11];
    const float* ch_wz_b = (const float*)d_in[12];
    const float* ln_g    = (const float*)d_in[13];
    const float* ln_b    = (const float*)d_in[14];
    const float* sp_wv_w = (const float*)d_in[15];
    const float* sp_wv_b = (const float*)d_in[16];
    const float* sp_wq_w = (const float*)d_in[17];
    const float* sp_wq_b = (const float*)d_in[18];

    float *p_expx, *p_bc, *p_pos;
    __nv_bfloat16 *p_WexpH, *p_WexpL, *p_WcatH, *p_WcatL;
    cudaGetSymbolAddress((void**)&p_expx, g_expx);
    cudaGetSymbolAddress((void**)&p_bc, g_bc);
    cudaGetSymbolAddress((void**)&p_pos, g_pos);
    cudaGetSymbolAddress((void**)&p_WexpH, g_WexpH);
    cudaGetSymbolAddress((void**)&p_WexpL, g_WexpL);
    cudaGetSymbolAddress((void**)&p_WcatH, g_WcatH);
    cudaGetSymbolAddress((void**)&p_WcatL, g_WcatL);

    cudaFuncSetAttribute(gemm_mma4,
                         cudaFuncAttributeMaxDynamicSharedMemorySize, SM_BYTES);
    cudaFuncSetAttribute(gemm_fin,
                         cudaFuncAttributeMaxDynamicSharedMemorySize, FSM_BYTES);

    pos_kernel<<<(C * P) / 256, 256>>>();
    wcat_kernel<<<KFULL + 1, 256>>>(w_fus, w_res, b_res, b_fus);
    wsplit_kernel<<<(COUT3 * C) / 1024, 256>>>(w_exp, p_WexpH, p_WexpL, COUT3 * C);
    xprep_kernel<<<dim3(P / 32, C / 32, NB), 256>>>(x);

    // g_expx = X = W_exp @ x + b_exp + pos  (pos fused in epilogue)
    gemm_mma4<<<dim3(P / 128, COUT3 / 128, NB), 256, SM_BYTES>>>(
        p_WexpH, p_WexpL, b_exp, p_expx, C, COUT3, p_pos);

    tqred_kernel<<<dim3(P / 128, NB, 3), 256>>>(ch_wq_w, ch_wq_b);
    tiny_kernel<<<dim3(NB, 3), 256>>>(ch_wv_w, ch_wv_b, ch_wz_w, ch_wz_b,
                                      ln_g, ln_b, sp_wq_w, sp_wq_b,
                                      sp_wv_w, sp_wv_b);

    // out = [Wc | W_fus] @ [gated-cat ; x] + bc   (N=128, single-barrier ring)
    gemm_fin<<<dim3(P / 128, 1, NB), 512, FSM_BYTES>>>(
        p_WcatH, p_WcatL, p_bc, (float*)d_out);
}